// round 9
// baseline (speedup 1.0000x reference)
#include <cuda_runtime.h>
#include <cstddef>

#define N_USER  100000
#define N_MOVIE 20000
#define D_IN    64
#define HID     128
#define OUT_D   64
#define NEDGE   600000

typedef unsigned long long ULL;

// ---------------------------------------------------------------------------
// Scratch
// ---------------------------------------------------------------------------
__device__ int g_deg_u[N_USER];
__device__ int g_deg_m[N_MOVIE];
__device__ int g_off_u[N_USER];
__device__ int g_off_m[N_MOVIE];
__device__ int g_cur_u[N_USER];
__device__ int g_cur_m[N_MOVIE];
__device__ int g_adj_u[NEDGE];
__device__ int g_adj_m[NEDGE];
__device__ int g_part_u[128];
__device__ int g_part_m[32];

__device__ float g_agg_user [N_USER  * D_IN];
__device__ float g_agg_movie[N_MOVIE * D_IN];
__device__ float g_agg_user2[N_USER  * HID];
__device__ float g_user_x  [N_USER  * HID];
__device__ float g_movie_x [N_MOVIE * HID];
__device__ float g_movieP  [N_MOVIE * HID];
__device__ float g_user_h  [N_USER  * HID];

// ---------------------------------------------------------------------------
// Packed f32x2 helpers
// ---------------------------------------------------------------------------
__device__ __forceinline__ ULL pack2(float x, float y) {
    ULL r;
    asm("mov.b64 %0, {%1, %2};" : "=l"(r) : "f"(x), "f"(y));
    return r;
}
__device__ __forceinline__ float2 unpack2(ULL v) {
    float2 r;
    asm("mov.b64 {%0, %1}, %2;" : "=f"(r.x), "=f"(r.y) : "l"(v));
    return r;
}
__device__ __forceinline__ ULL ffma2u(ULL a, ULL b, ULL c) {
    ULL d;
    asm("fma.rn.f32x2 %0, %1, %2, %3;" : "=l"(d) : "l"(a), "l"(b), "l"(c));
    return d;
}

// ---------------------------------------------------------------------------
// CSR build
// ---------------------------------------------------------------------------
__global__ void zero_counts() {
    int i = blockIdx.x * blockDim.x + threadIdx.x;
    if (i < N_USER)  g_deg_u[i] = 0;
    if (i < N_MOVIE) g_deg_m[i] = 0;
}

__global__ __launch_bounds__(256) void hist_kernel(
    const int* __restrict__ eu, const int* __restrict__ em)
{
    int e = blockIdx.x * blockDim.x + threadIdx.x;
    if (e >= NEDGE) return;
    atomicAdd(&g_deg_u[eu[e]], 1);
    atomicAdd(&g_deg_m[em[e]], 1);
}

__device__ __forceinline__ void scan_dev(
    const int* __restrict__ deg, int* __restrict__ off,
    int* __restrict__ part, int n, int blk)
{
    __shared__ int s[1024];
    int t = threadIdx.x;
    int i = blk * 1024 + t;
    int v = (i < n) ? deg[i] : 0;
    s[t] = v;
    __syncthreads();
    #pragma unroll
    for (int d = 1; d < 1024; d <<= 1) {
        int x = (t >= d) ? s[t - d] : 0;
        __syncthreads();
        s[t] += x;
        __syncthreads();
    }
    if (i < n) off[i] = s[t] - v;
    if (t == 1023) part[blk] = s[1023];
}

#define NBU ((N_USER  + 1023) / 1024)   // 98
#define NBM ((N_MOVIE + 1023) / 1024)   // 20

__global__ __launch_bounds__(1024) void scan_both_kernel() {
    if (blockIdx.x < NBU) scan_dev(g_deg_u, g_off_u, g_part_u, N_USER, blockIdx.x);
    else                  scan_dev(g_deg_m, g_off_m, g_part_m, N_MOVIE, blockIdx.x - NBU);
}

__global__ __launch_bounds__(128) void scan_partials_kernel() {
    __shared__ int s[128];
    int t = threadIdx.x;
    int v = (t < NBU) ? g_part_u[t] : 0;
    s[t] = v;
    __syncthreads();
    #pragma unroll
    for (int d = 1; d < 128; d <<= 1) {
        int x = (t >= d) ? s[t - d] : 0;
        __syncthreads();
        s[t] += x;
        __syncthreads();
    }
    if (t < NBU) g_part_u[t] = s[t] - v;
    __syncthreads();
    v = (t < NBM) ? g_part_m[t] : 0;
    s[t] = v;
    __syncthreads();
    #pragma unroll
    for (int d = 1; d < 128; d <<= 1) {
        int x = (t >= d) ? s[t - d] : 0;
        __syncthreads();
        s[t] += x;
        __syncthreads();
    }
    if (t < NBM) g_part_m[t] = s[t] - v;
}

__global__ __launch_bounds__(256) void add_offsets_both() {
    int i = blockIdx.x * blockDim.x + threadIdx.x;
    if (i < N_USER) {
        int o = g_off_u[i] + g_part_u[i >> 10];
        g_off_u[i] = o;
        g_cur_u[i] = o;
    } else if (i < N_USER + N_MOVIE) {
        int j = i - N_USER;
        int o = g_off_m[j] + g_part_m[j >> 10];
        g_off_m[j] = o;
        g_cur_m[j] = o;
    }
}

__global__ __launch_bounds__(256) void fill_kernel(
    const int* __restrict__ eu, const int* __restrict__ em)
{
    int e = blockIdx.x * blockDim.x + threadIdx.x;
    if (e >= NEDGE) return;
    int u = eu[e], m = em[e];
    int su = atomicAdd(&g_cur_u[u], 1);
    g_adj_u[su] = m;
    int sm = atomicAdd(&g_cur_m[m], 1);
    g_adj_m[sm] = u;
}

// ---------------------------------------------------------------------------
// Subwarp gather-mean (measured R6: gatherA+gatherB ~= 80us total)
// ---------------------------------------------------------------------------
#define DEG_CLAMP 2048

template<int D, int SUBW>
__device__ __forceinline__ void gather_dev(
    const float* __restrict__ src, const int* __restrict__ adj,
    const int* __restrict__ off, const int* __restrict__ deg,
    float* __restrict__ dst, int n, int n_src, int gwarp, int lane)
{
    constexpr int NPW = 32 / SUBW;
    constexpr int VEC = D / SUBW;
    const int sw = lane / SUBW;
    const int sl = lane - sw * SUBW;
    const int node = gwarp * NPW + sw;
    const bool valid = node < n;
    const int nd = valid ? node : (n - 1);
    int o = __ldg(&off[nd]);
    o = min(max(o, 0), NEDGE - 1);
    int d = valid ? __ldg(&deg[nd]) : 0;
    d = min(max(d, 0), DEG_CLAMP);

    int dmax = d;
    #pragma unroll
    for (int k = 16; k; k >>= 1)
        dmax = max(dmax, __shfl_xor_sync(0xffffffffu, dmax, k));

    float acc[VEC];
    #pragma unroll
    for (int v = 0; v < VEC; v++) acc[v] = 0.f;

    const int subbase = sw * SUBW;
    for (int base = 0; base < dmax; base += SUBW) {
        int idx = 0;
        int pos = o + base + sl;
        if (base + sl < d && pos < NEDGE) idx = __ldg(&adj[pos]);
        idx = min(max(idx, 0), n_src - 1);
        const int lim = min(dmax - base, SUBW);
        #pragma unroll 4
        for (int i = 0; i < lim; i++) {
            int s = __shfl_sync(0xffffffffu, idx, subbase + i);
            if (base + i < d) {
                const float* row = src + (size_t)s * D + sl * VEC;
                if constexpr (VEC == 8) {
                    float4 a = __ldg((const float4*)row);
                    float4 b = __ldg((const float4*)(row + 4));
                    acc[0] += a.x; acc[1] += a.y; acc[2] += a.z; acc[3] += a.w;
                    acc[4] += b.x; acc[5] += b.y; acc[6] += b.z; acc[7] += b.w;
                } else {
                    float2 a = __ldg((const float2*)row);
                    acc[0] += a.x; acc[1] += a.y;
                }
            }
        }
    }

    if (valid) {
        float sc = 1.0f / (float)max(d, 1);
        float* out = dst + (size_t)node * D + sl * VEC;
        if constexpr (VEC == 8) {
            *(float4*)out       = make_float4(acc[0]*sc, acc[1]*sc, acc[2]*sc, acc[3]*sc);
            *(float4*)(out + 4) = make_float4(acc[4]*sc, acc[5]*sc, acc[6]*sc, acc[7]*sc);
        } else {
            *(float2*)out = make_float2(acc[0]*sc, acc[1]*sc);
        }
    }
}

#define UWARPS ((N_USER + 3) / 4)
#define GA_WARPS (UWARPS + N_MOVIE)

__global__ __launch_bounds__(256) void gatherA(
    const float* __restrict__ x_movie, const float* __restrict__ x_user)
{
    int gw = (blockIdx.x * 256 + threadIdx.x) >> 5;
    int lane = threadIdx.x & 31;
    if (gw < UWARPS) {
        gather_dev<D_IN, 8>(x_movie, g_adj_u, g_off_u, g_deg_u,
                            g_agg_user, N_USER, N_MOVIE, gw, lane);
    } else if (gw < GA_WARPS) {
        gather_dev<D_IN, 32>(x_user, g_adj_m, g_off_m, g_deg_m,
                             g_agg_movie, N_MOVIE, N_USER, gw - UWARPS, lane);
    }
}

#define GB_WARPS ((N_USER + 1) / 2)

__global__ __launch_bounds__(256) void gatherB() {
    int gw = (blockIdx.x * 256 + threadIdx.x) >> 5;
    int lane = threadIdx.x & 31;
    if (gw < GB_WARPS) {
        gather_dev<HID, 16>(g_movieP, g_adj_u, g_off_u, g_deg_u,
                            g_agg_user2, N_USER, N_MOVIE, gw, lane);
    }
}

// ---------------------------------------------------------------------------
// R1-style combine (MEASURED 52.5us for conv1 shape): smem-staged weights
// AND smem-staged duplicated row pairs; 8 rows/tile; 2D block (CP x YG).
//   out[r] = act( [WL: agg[r]@Wl] + [AGG&&!WL: agg[r] direct] + x[r]@Wr + b )
// agg is already the mean.
// ---------------------------------------------------------------------------
template<int K, int N, bool WL, bool AGG, bool RELU, bool BIAS>
__global__ __launch_bounds__(256) void combine_kernel(
    const float* __restrict__ agg, const float* __restrict__ x,
    const float* __restrict__ Wl, const float* __restrict__ Wr,
    const float* __restrict__ bias,
    float* __restrict__ out, int nrows)
{
    constexpr int CP   = N / 2;        // column pairs
    constexpr int YG   = 256 / CP;     // row groups
    constexpr int ROWS = 8;            // rows per block iteration
    constexpr int RPT  = ROWS / YG;    // rows per thread

    extern __shared__ __align__(16) char smem[];
    float* sWr = (float*)smem;                       // [K][N]
    float* sWl = sWr + K * N;                        // [K][N] (only if WL)
    ULL* sx = (ULL*)(smem + (size_t)(WL ? 2 : 1) * K * N * 4);
    ULL* sa = sx + ROWS * K;                         // only if WL

    const int tid = threadIdx.y * CP + threadIdx.x;

    // Stage weights once per block
    for (int i = tid; i < K * N / 4; i += 256) {
        ((float4*)sWr)[i] = ((const float4*)Wr)[i];
        if constexpr (WL) ((float4*)sWl)[i] = ((const float4*)Wl)[i];
    }

    const int ntiles = (nrows + ROWS - 1) / ROWS;
    for (int tile = blockIdx.x; tile < ntiles; tile += gridDim.x) {
        const int row0 = tile * ROWS;
        __syncthreads();   // also covers the initial weight staging
        // Stage 8 rows of x (and agg) as duplicated f32 pairs
        for (int i = tid; i < ROWS * K; i += 256) {
            int r = i / K, k = i - r * K;
            int row = row0 + r;
            float v = 0.f, va = 0.f;
            if (row < nrows) {
                v = x[(size_t)row * K + k];
                if constexpr (WL) va = agg[(size_t)row * K + k];
            }
            sx[i] = pack2(v, v);
            if constexpr (WL) sa[i] = pack2(va, va);
        }
        __syncthreads();

        const int c  = threadIdx.x;
        const int yy = threadIdx.y;
        ULL acc[RPT];
        #pragma unroll
        for (int r = 0; r < RPT; r++) {
            int row = row0 + yy * RPT + r;
            float2 a0 = make_float2(0.f, 0.f);
            if constexpr (BIAS) a0 = ((const float2*)bias)[c];
            if constexpr (AGG && !WL) {
                if (row < nrows) {
                    float2 g = ((const float2*)agg)[(size_t)row * CP + c];
                    a0.x += g.x;
                    a0.y += g.y;
                }
            }
            acc[r] = pack2(a0.x, a0.y);
        }

        const ULL* sWr2 = (const ULL*)sWr;
        const ULL* sWl2 = (const ULL*)sWl;
        #pragma unroll 8
        for (int k = 0; k < K; k++) {
            ULL wr2 = sWr2[k * CP + c];
            ULL wl2 = 0;
            if constexpr (WL) wl2 = sWl2[k * CP + c];
            #pragma unroll
            for (int r = 0; r < RPT; r++) {
                int rl = yy * RPT + r;
                acc[r] = ffma2u(sx[rl * K + k], wr2, acc[r]);
                if constexpr (WL) acc[r] = ffma2u(sa[rl * K + k], wl2, acc[r]);
            }
        }

        #pragma unroll
        for (int r = 0; r < RPT; r++) {
            int row = row0 + yy * RPT + r;
            if (row < nrows) {
                float2 o = unpack2(acc[r]);
                if constexpr (RELU) { o.x = fmaxf(o.x, 0.f); o.y = fmaxf(o.y, 0.f); }
                ((float2*)out)[(size_t)row * CP + c] = o;
            }
        }
    }
}

// ---------------------------------------------------------------------------
// kernel_launch
// ---------------------------------------------------------------------------
extern "C" void kernel_launch(void* const* d_in, const int* in_sizes, int n_in,
                              void* d_out, int out_size) {
    const float* x_user  = (const float*)d_in[0];
    const float* x_movie = (const float*)d_in[1];
    const int*   eu      = (const int*)d_in[2];
    const int*   em      = (const int*)d_in[3];
    const float* W1l     = (const float*)d_in[4];
    const float* W1r     = (const float*)d_in[5];
    const float* b1      = (const float*)d_in[6];
    const float* W2l     = (const float*)d_in[7];
    const float* W2r     = (const float*)d_in[8];
    const float* b2      = (const float*)d_in[9];
    const float* W3l     = (const float*)d_in[10];
    const float* W3r     = (const float*)d_in[11];
    const float* b3      = (const float*)d_in[12];
    const float* Wlin1   = (const float*)d_in[13];
    const float* blin1   = (const float*)d_in[14];
    const float* Wlin2   = (const float*)d_in[15];
    const float* blin2   = (const float*)d_in[16];

    float* out_user  = (float*)d_out;
    float* out_movie = out_user + (size_t)N_USER * OUT_D;

    float *p_agg_user, *p_agg_movie, *p_agg_user2;
    float *p_user_x, *p_movie_x, *p_movieP, *p_user_h;
    cudaGetSymbolAddress((void**)&p_agg_user,  g_agg_user);
    cudaGetSymbolAddress((void**)&p_agg_movie, g_agg_movie);
    cudaGetSymbolAddress((void**)&p_agg_user2, g_agg_user2);
    cudaGetSymbolAddress((void**)&p_user_x,    g_user_x);
    cudaGetSymbolAddress((void**)&p_movie_x,   g_movie_x);
    cudaGetSymbolAddress((void**)&p_movieP,    g_movieP);
    cudaGetSymbolAddress((void**)&p_user_h,    g_user_h);

    // smem sizes (weights + duplicated-pair row staging), as in R1
    const int SM_CONV12 = 2 * D_IN * HID * 4 + 8 * D_IN * 8 * 2;  // 73728
    const int SM_HH     = HID * HID * 4 + 8 * HID * 8;            // 73728
    const int SM_HO     = HID * OUT_D * 4 + 8 * HID * 8;          // 40960

    cudaFuncSetAttribute((const void*)combine_kernel<D_IN, HID, true,  true,  true,  true>,
                         cudaFuncAttributeMaxDynamicSharedMemorySize, SM_CONV12);
    cudaFuncSetAttribute((const void*)combine_kernel<HID, HID, false, false, false, false>,
                         cudaFuncAttributeMaxDynamicSharedMemorySize, SM_HH);
    cudaFuncSetAttribute((const void*)combine_kernel<HID, HID, false, true,  true,  true>,
                         cudaFuncAttributeMaxDynamicSharedMemorySize, SM_HH);
    cudaFuncSetAttribute((const void*)combine_kernel<HID, OUT_D, false, false, false, true>,
                         cudaFuncAttributeMaxDynamicSharedMemorySize, SM_HO);

    const int GRID_PERSIST = 444;   // ~3 blocks/SM at 72KB smem (R1-measured config)

    // CSR build
    zero_counts<<<(N_USER + 255) / 256, 256>>>();
    hist_kernel<<<(NEDGE + 255) / 256, 256>>>(eu, em);
    scan_both_kernel<<<NBU + NBM, 1024>>>();
    scan_partials_kernel<<<1, 128>>>();
    add_offsets_both<<<(N_USER + N_MOVIE + 255) / 256, 256>>>();
    fill_kernel<<<(NEDGE + 255) / 256, 256>>>(eu, em);

    // conv1 + conv2 aggregation (fused subwarp gathers)
    gatherA<<<(GA_WARPS * 32 + 255) / 256, 256>>>(x_movie, x_user);

    // conv1: user_x = relu(agg_user @ W1l + x_user @ W1r + b1)
    combine_kernel<D_IN, HID, true, true, true, true>
        <<<GRID_PERSIST, dim3(HID / 2, 256 / (HID / 2)), SM_CONV12>>>(
            p_agg_user, x_user, W1l, W1r, b1, p_user_x, N_USER);

    // conv2: movie_x = relu(agg_movie @ W2l + x_movie @ W2r + b2)
    combine_kernel<D_IN, HID, true, true, true, true>
        <<<GRID_PERSIST, dim3(HID / 2, 256 / (HID / 2)), SM_CONV12>>>(
            p_agg_movie, x_movie, W2l, W2r, b2, p_movie_x, N_MOVIE);

    // movieP = movie_x @ W3l (projected before aggregation)
    combine_kernel<HID, HID, false, false, false, false>
        <<<GRID_PERSIST, dim3(HID / 2, 256 / (HID / 2)), SM_HH>>>(
            nullptr, p_movie_x, nullptr, W3l, nullptr, p_movieP, N_MOVIE);

    // conv3 aggregation (subwarp gather of projected features)
    gatherB<<<(GB_WARPS * 32 + 255) / 256, 256>>>();

    // conv3: user_h = relu(agg_user2 + user_x @ W3r + b3)
    combine_kernel<HID, HID, false, true, true, true>
        <<<GRID_PERSIST, dim3(HID / 2, 256 / (HID / 2)), SM_HH>>>(
            p_agg_user2, p_user_x, nullptr, W3r, b3, p_user_h, N_USER);

    // out_user = user_h @ Wlin1 + blin1
    combine_kernel<HID, OUT_D, false, false, false, true>
        <<<GRID_PERSIST, dim3(OUT_D / 2, 256 / (OUT_D / 2)), SM_HO>>>(
            nullptr, p_user_h, nullptr, Wlin1, blin1, out_user, N_USER);

    // out_movie = movie_x @ Wlin2 + blin2
    combine_kernel<HID, OUT_D, false, false, false, true>
        <<<GRID_PERSIST, dim3(OUT_D / 2, 256 / (OUT_D / 2)), SM_HO>>>(
            nullptr, p_movie_x, nullptr, Wlin2, blin2, out_movie, N_MOVIE);
}

// round 10
// speedup vs baseline: 1.7898x; 1.7898x over previous
#include <cuda_runtime.h>
#include <cstddef>

#define N_USER  100000
#define N_MOVIE 20000
#define D_IN    64
#define HID     128
#define OUT_D   64
#define NEDGE   600000

typedef unsigned long long ULL;

// ---------------------------------------------------------------------------
// Scratch
// ---------------------------------------------------------------------------
__device__ int g_deg_u[N_USER];
__device__ int g_deg_m[N_MOVIE];
__device__ int g_off_u[N_USER];
__device__ int g_off_m[N_MOVIE];
__device__ int g_cur_u[N_USER];
__device__ int g_cur_m[N_MOVIE];
__device__ int g_adj_u[NEDGE];
__device__ int g_adj_m[NEDGE];
__device__ int g_part_u[128];
__device__ int g_part_m[32];

__device__ float g_agg_user [N_USER  * D_IN];
__device__ float g_agg_movie[N_MOVIE * D_IN];
__device__ float g_agg_user2[N_USER  * HID];
__device__ float g_user_x  [N_USER  * HID];
__device__ float g_movie_x [N_MOVIE * HID];
__device__ float g_movieP  [N_MOVIE * HID];
__device__ float g_user_h  [N_USER  * HID];

// ---------------------------------------------------------------------------
// Packed f32x2 helpers
// ---------------------------------------------------------------------------
__device__ __forceinline__ ULL pack2(float x, float y) {
    ULL r;
    asm("mov.b64 %0, {%1, %2};" : "=l"(r) : "f"(x), "f"(y));
    return r;
}
__device__ __forceinline__ float2 unpack2(ULL v) {
    float2 r;
    asm("mov.b64 {%0, %1}, %2;" : "=f"(r.x), "=f"(r.y) : "l"(v));
    return r;
}
__device__ __forceinline__ ULL ffma2u(ULL a, ULL b, ULL c) {
    ULL d;
    asm("fma.rn.f32x2 %0, %1, %2, %3;" : "=l"(d) : "l"(a), "l"(b), "l"(c));
    return d;
}

// ---------------------------------------------------------------------------
// CSR build
// ---------------------------------------------------------------------------
__global__ void zero_counts() {
    int i = blockIdx.x * blockDim.x + threadIdx.x;
    if (i < N_USER)  g_deg_u[i] = 0;
    if (i < N_MOVIE) g_deg_m[i] = 0;
}

__global__ __launch_bounds__(256) void hist_kernel(
    const int* __restrict__ eu, const int* __restrict__ em)
{
    int e = blockIdx.x * blockDim.x + threadIdx.x;
    if (e >= NEDGE) return;
    atomicAdd(&g_deg_u[eu[e]], 1);
    atomicAdd(&g_deg_m[em[e]], 1);
}

__device__ __forceinline__ void scan_dev(
    const int* __restrict__ deg, int* __restrict__ off,
    int* __restrict__ part, int n, int blk)
{
    __shared__ int s[1024];
    int t = threadIdx.x;
    int i = blk * 1024 + t;
    int v = (i < n) ? deg[i] : 0;
    s[t] = v;
    __syncthreads();
    #pragma unroll
    for (int d = 1; d < 1024; d <<= 1) {
        int x = (t >= d) ? s[t - d] : 0;
        __syncthreads();
        s[t] += x;
        __syncthreads();
    }
    if (i < n) off[i] = s[t] - v;
    if (t == 1023) part[blk] = s[1023];
}

#define NBU ((N_USER  + 1023) / 1024)   // 98
#define NBM ((N_MOVIE + 1023) / 1024)   // 20

__global__ __launch_bounds__(1024) void scan_both_kernel() {
    if (blockIdx.x < NBU) scan_dev(g_deg_u, g_off_u, g_part_u, N_USER, blockIdx.x);
    else                  scan_dev(g_deg_m, g_off_m, g_part_m, N_MOVIE, blockIdx.x - NBU);
}

__global__ __launch_bounds__(128) void scan_partials_kernel() {
    __shared__ int s[128];
    int t = threadIdx.x;
    int v = (t < NBU) ? g_part_u[t] : 0;
    s[t] = v;
    __syncthreads();
    #pragma unroll
    for (int d = 1; d < 128; d <<= 1) {
        int x = (t >= d) ? s[t - d] : 0;
        __syncthreads();
        s[t] += x;
        __syncthreads();
    }
    if (t < NBU) g_part_u[t] = s[t] - v;
    __syncthreads();
    v = (t < NBM) ? g_part_m[t] : 0;
    s[t] = v;
    __syncthreads();
    #pragma unroll
    for (int d = 1; d < 128; d <<= 1) {
        int x = (t >= d) ? s[t - d] : 0;
        __syncthreads();
        s[t] += x;
        __syncthreads();
    }
    if (t < NBM) g_part_m[t] = s[t] - v;
}

__global__ __launch_bounds__(256) void add_offsets_both() {
    int i = blockIdx.x * blockDim.x + threadIdx.x;
    if (i < N_USER) {
        int o = g_off_u[i] + g_part_u[i >> 10];
        g_off_u[i] = o;
        g_cur_u[i] = o;
    } else if (i < N_USER + N_MOVIE) {
        int j = i - N_USER;
        int o = g_off_m[j] + g_part_m[j >> 10];
        g_off_m[j] = o;
        g_cur_m[j] = o;
    }
}

__global__ __launch_bounds__(256) void fill_kernel(
    const int* __restrict__ eu, const int* __restrict__ em)
{
    int e = blockIdx.x * blockDim.x + threadIdx.x;
    if (e >= NEDGE) return;
    int u = eu[e], m = em[e];
    int su = atomicAdd(&g_cur_u[u], 1);
    g_adj_u[su] = m;
    int sm = atomicAdd(&g_cur_m[m], 1);
    g_adj_m[sm] = u;
}

// ---------------------------------------------------------------------------
// Subwarp gather-mean (measured R6: gatherA+gatherB ~= 80us total)
// ---------------------------------------------------------------------------
#define DEG_CLAMP 2048

template<int D, int SUBW>
__device__ __forceinline__ void gather_dev(
    const float* __restrict__ src, const int* __restrict__ adj,
    const int* __restrict__ off, const int* __restrict__ deg,
    float* __restrict__ dst, int n, int n_src, int gwarp, int lane)
{
    constexpr int NPW = 32 / SUBW;
    constexpr int VEC = D / SUBW;
    const int sw = lane / SUBW;
    const int sl = lane - sw * SUBW;
    const int node = gwarp * NPW + sw;
    const bool valid = node < n;
    const int nd = valid ? node : (n - 1);
    int o = __ldg(&off[nd]);
    o = min(max(o, 0), NEDGE - 1);
    int d = valid ? __ldg(&deg[nd]) : 0;
    d = min(max(d, 0), DEG_CLAMP);

    int dmax = d;
    #pragma unroll
    for (int k = 16; k; k >>= 1)
        dmax = max(dmax, __shfl_xor_sync(0xffffffffu, dmax, k));

    float acc[VEC];
    #pragma unroll
    for (int v = 0; v < VEC; v++) acc[v] = 0.f;

    const int subbase = sw * SUBW;
    for (int base = 0; base < dmax; base += SUBW) {
        int idx = 0;
        int pos = o + base + sl;
        if (base + sl < d && pos < NEDGE) idx = __ldg(&adj[pos]);
        idx = min(max(idx, 0), n_src - 1);
        const int lim = min(dmax - base, SUBW);
        #pragma unroll 4
        for (int i = 0; i < lim; i++) {
            int s = __shfl_sync(0xffffffffu, idx, subbase + i);
            if (base + i < d) {
                const float* row = src + (size_t)s * D + sl * VEC;
                if constexpr (VEC == 8) {
                    float4 a = __ldg((const float4*)row);
                    float4 b = __ldg((const float4*)(row + 4));
                    acc[0] += a.x; acc[1] += a.y; acc[2] += a.z; acc[3] += a.w;
                    acc[4] += b.x; acc[5] += b.y; acc[6] += b.z; acc[7] += b.w;
                } else {
                    float2 a = __ldg((const float2*)row);
                    acc[0] += a.x; acc[1] += a.y;
                }
            }
        }
    }

    if (valid) {
        float sc = 1.0f / (float)max(d, 1);
        float* out = dst + (size_t)node * D + sl * VEC;
        if constexpr (VEC == 8) {
            *(float4*)out       = make_float4(acc[0]*sc, acc[1]*sc, acc[2]*sc, acc[3]*sc);
            *(float4*)(out + 4) = make_float4(acc[4]*sc, acc[5]*sc, acc[6]*sc, acc[7]*sc);
        } else {
            *(float2*)out = make_float2(acc[0]*sc, acc[1]*sc);
        }
    }
}

#define UWARPS ((N_USER + 3) / 4)
#define GA_WARPS (UWARPS + N_MOVIE)

__global__ __launch_bounds__(256) void gatherA(
    const float* __restrict__ x_movie, const float* __restrict__ x_user)
{
    int gw = (blockIdx.x * 256 + threadIdx.x) >> 5;
    int lane = threadIdx.x & 31;
    if (gw < UWARPS) {
        gather_dev<D_IN, 8>(x_movie, g_adj_u, g_off_u, g_deg_u,
                            g_agg_user, N_USER, N_MOVIE, gw, lane);
    } else if (gw < GA_WARPS) {
        gather_dev<D_IN, 32>(x_user, g_adj_m, g_off_m, g_deg_m,
                             g_agg_movie, N_MOVIE, N_USER, gw - UWARPS, lane);
    }
}

#define GB_WARPS ((N_USER + 1) / 2)

__global__ __launch_bounds__(256) void gatherB() {
    int gw = (blockIdx.x * 256 + threadIdx.x) >> 5;
    int lane = threadIdx.x & 31;
    if (gw < GB_WARPS) {
        gather_dev<HID, 16>(g_movieP, g_adj_u, g_off_u, g_deg_u,
                            g_agg_user2, N_USER, N_MOVIE, gw, lane);
    }
}

// ---------------------------------------------------------------------------
// combine3: row-pair-packed f32x2 GEMM.
//   out[M,N] = act( A[M,128] @ W[128,N] (+agg direct) (+bias) )
//   A = [agg|x] (TWO, two K=64 sources) or x (K=128).
// x staged in smem as sx[rp][k] = pack2(row_{2rp}[k], row_{2rp+1}[k])  (no dup)
// Weights plain floats sW[c][KP] (KP=130, conflict-free LDS.64 per 2k).
// Each lane: 2 columns (c0=cg*64+lane, c1=c0+32) x RPW row-pairs.
// FFMA2 accumulates TWO ROWS per instruction -> issue-bound at f32x2 peak.
// ---------------------------------------------------------------------------
#define KC  128      // K of every GEMM in this net
#define KP  130      // padded K for weight smem

template<int N, bool TWO, bool AGG, bool RELU, bool BIAS>
__global__ __launch_bounds__(256) void combine3(
    const float* __restrict__ agg, const float* __restrict__ x,
    const float* __restrict__ Wl, const float* __restrict__ Wr,
    const float* __restrict__ bias,
    float* __restrict__ out, int nrows)
{
    constexpr int CGRP = N / 64;        // col groups (2 for N=128, 1 for N=64)
    constexpr int RGRP = 8 / CGRP;      // row groups
    constexpr int RPW  = 32 / RGRP;     // row-pairs per warp (8 or 4)

    extern __shared__ __align__(16) char smem[];
    float* sW = (float*)smem;                       // [N][KP]
    ULL*   sx = (ULL*)(smem + (size_t)N * KP * 4);  // [32 rp][KC]

    const int tid  = threadIdx.x;
    const int wid  = tid >> 5;
    const int lane = tid & 31;
    const int cg   = wid % CGRP;
    const int rg   = wid / CGRP;
    const int c0   = cg * 64 + lane;
    const int c1   = c0 + 32;

    // Stage weights once per persistent block: sW[c][k] = W[k][c]
    for (int i = tid; i < KC * N; i += 256) {
        int k = i / N, c = i % N;
        float w;
        if constexpr (TWO) {
            w = (k < 64) ? Wl[(size_t)k * N + c] : Wr[(size_t)(k - 64) * N + c];
        } else {
            w = Wr[(size_t)k * N + c];
        }
        sW[(size_t)c * KP + k] = w;
    }

    float b0 = 0.f, b1 = 0.f;
    if constexpr (BIAS) { b0 = bias[c0]; b1 = bias[c1]; }

    const int ntiles = (nrows + 63) / 64;
    for (int tile = blockIdx.x; tile < ntiles; tile += gridDim.x) {
        const int row0 = tile * 64;
        __syncthreads();   // covers initial weight staging too
        // Stage 64 rows as row-pair packs: sx[rp][k] = (row_{2rp}[k], row_{2rp+1}[k])
        for (int i = tid; i < 32 * KC; i += 256) {
            int rp = i >> 7, k = i & 127;
            int ra = min(row0 + 2 * rp,     nrows - 1);
            int rb = min(row0 + 2 * rp + 1, nrows - 1);
            float va, vb;
            if constexpr (TWO) {
                if (k < 64) {
                    va = agg[(size_t)ra * 64 + k];
                    vb = agg[(size_t)rb * 64 + k];
                } else {
                    va = x[(size_t)ra * 64 + (k - 64)];
                    vb = x[(size_t)rb * 64 + (k - 64)];
                }
            } else {
                va = x[(size_t)ra * KC + k];
                vb = x[(size_t)rb * KC + k];
            }
            sx[i] = pack2(va, vb);
        }
        __syncthreads();

        ULL acc[2][RPW];
        #pragma unroll
        for (int r = 0; r < RPW; r++) {
            acc[0][r] = pack2(b0, b0);
            acc[1][r] = pack2(b1, b1);
        }

        const ULL* sxr = sx + (size_t)(rg * RPW) * KC;
        const float* w0p = sW + (size_t)c0 * KP;
        const float* w1p = sW + (size_t)c1 * KP;

        #pragma unroll 2
        for (int k = 0; k < KC; k += 2) {
            float2 w0 = *(const float2*)(w0p + k);
            float2 w1 = *(const float2*)(w1p + k);
            ULL w00 = pack2(w0.x, w0.x), w01 = pack2(w0.y, w0.y);
            ULL w10 = pack2(w1.x, w1.x), w11 = pack2(w1.y, w1.y);
            #pragma unroll
            for (int r = 0; r < RPW; r++) {
                ulonglong2 xv = *(const ulonglong2*)(sxr + (size_t)r * KC + k);
                acc[0][r] = ffma2u(xv.x, w00, acc[0][r]);
                acc[0][r] = ffma2u(xv.y, w01, acc[0][r]);
                acc[1][r] = ffma2u(xv.x, w10, acc[1][r]);
                acc[1][r] = ffma2u(xv.y, w11, acc[1][r]);
            }
        }

        // Epilogue: acc[j][r] = (out[rowa][cj], out[rowb][cj])
        #pragma unroll
        for (int r = 0; r < RPW; r++) {
            int rowa = row0 + (rg * RPW + r) * 2;
            int rowb = rowa + 1;
            #pragma unroll
            for (int j = 0; j < 2; j++) {
                int c = (j == 0) ? c0 : c1;
                float2 v = unpack2(acc[j][r]);
                if (rowa < nrows) {
                    float o = v.x;
                    if constexpr (AGG) o += agg[(size_t)rowa * N + c];
                    if constexpr (RELU) o = fmaxf(o, 0.f);
                    out[(size_t)rowa * N + c] = o;
                }
                if (rowb < nrows) {
                    float o = v.y;
                    if constexpr (AGG) o += agg[(size_t)rowb * N + c];
                    if constexpr (RELU) o = fmaxf(o, 0.f);
                    out[(size_t)rowb * N + c] = o;
                }
            }
        }
    }
}

// ---------------------------------------------------------------------------
// kernel_launch
// ---------------------------------------------------------------------------
extern "C" void kernel_launch(void* const* d_in, const int* in_sizes, int n_in,
                              void* d_out, int out_size) {
    const float* x_user  = (const float*)d_in[0];
    const float* x_movie = (const float*)d_in[1];
    const int*   eu      = (const int*)d_in[2];
    const int*   em      = (const int*)d_in[3];
    const float* W1l     = (const float*)d_in[4];
    const float* W1r     = (const float*)d_in[5];
    const float* b1      = (const float*)d_in[6];
    const float* W2l     = (const float*)d_in[7];
    const float* W2r     = (const float*)d_in[8];
    const float* b2      = (const float*)d_in[9];
    const float* W3l     = (const float*)d_in[10];
    const float* W3r     = (const float*)d_in[11];
    const float* b3      = (const float*)d_in[12];
    const float* Wlin1   = (const float*)d_in[13];
    const float* blin1   = (const float*)d_in[14];
    const float* Wlin2   = (const float*)d_in[15];
    const float* blin2   = (const float*)d_in[16];

    float* out_user  = (float*)d_out;
    float* out_movie = out_user + (size_t)N_USER * OUT_D;

    float *p_agg_user, *p_agg_movie, *p_agg_user2;
    float *p_user_x, *p_movie_x, *p_movieP, *p_user_h;
    cudaGetSymbolAddress((void**)&p_agg_user,  g_agg_user);
    cudaGetSymbolAddress((void**)&p_agg_movie, g_agg_movie);
    cudaGetSymbolAddress((void**)&p_agg_user2, g_agg_user2);
    cudaGetSymbolAddress((void**)&p_user_x,    g_user_x);
    cudaGetSymbolAddress((void**)&p_movie_x,   g_movie_x);
    cudaGetSymbolAddress((void**)&p_movieP,    g_movieP);
    cudaGetSymbolAddress((void**)&p_user_h,    g_user_h);

    // smem: weights [N][130] floats + x-pairs [32][128] ULL
    const int SM3_128 = 128 * KP * 4 + 32 * KC * 8;   // 66560 + 32768 = 99328
    const int SM3_64  = 64  * KP * 4 + 32 * KC * 8;   // 33280 + 32768 = 66048

    cudaFuncSetAttribute((const void*)combine3<128, true,  false, true,  true>,
                         cudaFuncAttributeMaxDynamicSharedMemorySize, SM3_128);
    cudaFuncSetAttribute((const void*)combine3<128, false, false, false, false>,
                         cudaFuncAttributeMaxDynamicSharedMemorySize, SM3_128);
    cudaFuncSetAttribute((const void*)combine3<128, false, true,  true,  true>,
                         cudaFuncAttributeMaxDynamicSharedMemorySize, SM3_128);
    cudaFuncSetAttribute((const void*)combine3<64,  false, false, false, true>,
                         cudaFuncAttributeMaxDynamicSharedMemorySize, SM3_64);

    const int GRID = 296;   // 2 persistent blocks/SM

    // CSR build
    zero_counts<<<(N_USER + 255) / 256, 256>>>();
    hist_kernel<<<(NEDGE + 255) / 256, 256>>>(eu, em);
    scan_both_kernel<<<NBU + NBM, 1024>>>();
    scan_partials_kernel<<<1, 128>>>();
    add_offsets_both<<<(N_USER + N_MOVIE + 255) / 256, 256>>>();
    fill_kernel<<<(NEDGE + 255) / 256, 256>>>(eu, em);

    // conv1 + conv2 aggregation (fused subwarp gathers)
    gatherA<<<(GA_WARPS * 32 + 255) / 256, 256>>>(x_movie, x_user);

    // conv1: user_x = relu([agg_user|x_user] @ [W1l;W1r] + b1)
    combine3<128, true, false, true, true><<<GRID, 256, SM3_128>>>(
        p_agg_user, x_user, W1l, W1r, b1, p_user_x, N_USER);

    // conv2: movie_x = relu([agg_movie|x_movie] @ [W2l;W2r] + b2)
    combine3<128, true, false, true, true><<<GRID, 256, SM3_128>>>(
        p_agg_movie, x_movie, W2l, W2r, b2, p_movie_x, N_MOVIE);

    // movieP = movie_x @ W3l (projected before aggregation)
    combine3<128, false, false, false, false><<<GRID, 256, SM3_128>>>(
        nullptr, p_movie_x, nullptr, W3l, nullptr, p_movieP, N_MOVIE);

    // conv3 aggregation (subwarp gather of projected features)
    gatherB<<<(GB_WARPS * 32 + 255) / 256, 256>>>();

    // conv3: user_h = relu(agg_user2 + user_x @ W3r + b3)
    combine3<128, false, true, true, true><<<GRID, 256, SM3_128>>>(
        p_agg_user2, p_user_x, nullptr, W3r, b3, p_user_h, N_USER);

    // out_user = user_h @ Wlin1 + blin1
    combine3<64, false, false, false, true><<<GRID, 256, SM3_64>>>(
        nullptr, p_user_h, nullptr, Wlin1, blin1, out_user, N_USER);

    // out_movie = movie_x @ Wlin2 + blin2
    combine3<64, false, false, false, true><<<GRID, 256, SM3_64>>>(
        nullptr, p_movie_x, nullptr, Wlin2, blin2, out_movie, N_MOVIE);
}

// round 14
// speedup vs baseline: 1.9231x; 1.0745x over previous
#include <cuda_runtime.h>
#include <cstddef>

#define N_USER  100000
#define N_MOVIE 20000
#define D_IN    64
#define HID     128
#define OUT_D   64
#define NEDGE   600000

typedef unsigned long long ULL;

// ---------------------------------------------------------------------------
// Scratch
// ---------------------------------------------------------------------------
__device__ int g_deg_u[N_USER];
__device__ int g_deg_m[N_MOVIE];
__device__ int g_off_u[N_USER];
__device__ int g_off_m[N_MOVIE];
__device__ int g_cur_u[N_USER];
__device__ int g_cur_m[N_MOVIE];
__device__ int g_adj_u[NEDGE];
__device__ int g_adj_m[NEDGE];
__device__ int g_part_u[128];
__device__ int g_part_m[32];

__device__ float g_agg_user [N_USER  * D_IN];
__device__ float g_agg_movie[N_MOVIE * D_IN];
__device__ float g_agg_user2[N_USER  * HID];
__device__ float g_user_x  [N_USER  * HID];
__device__ float g_movie_x [N_MOVIE * HID];
__device__ float g_movieP  [N_MOVIE * HID];
__device__ float g_user_h  [N_USER  * HID];

// ---------------------------------------------------------------------------
// Packed f32x2 helpers
// ---------------------------------------------------------------------------
__device__ __forceinline__ ULL pack2(float x, float y) {
    ULL r;
    asm("mov.b64 %0, {%1, %2};" : "=l"(r) : "f"(x), "f"(y));
    return r;
}
__device__ __forceinline__ float2 unpack2(ULL v) {
    float2 r;
    asm("mov.b64 {%0, %1}, %2;" : "=f"(r.x), "=f"(r.y) : "l"(v));
    return r;
}
__device__ __forceinline__ ULL ffma2u(ULL a, ULL b, ULL c) {
    ULL d;
    asm("fma.rn.f32x2 %0, %1, %2, %3;" : "=l"(d) : "l"(a), "l"(b), "l"(c));
    return d;
}

// ---------------------------------------------------------------------------
// CSR build (measured ~50us)
// ---------------------------------------------------------------------------
__global__ void zero_counts() {
    int i = blockIdx.x * blockDim.x + threadIdx.x;
    if (i < N_USER)  g_deg_u[i] = 0;
    if (i < N_MOVIE) g_deg_m[i] = 0;
}

__global__ __launch_bounds__(256) void hist_kernel(
    const int* __restrict__ eu, const int* __restrict__ em)
{
    int e = blockIdx.x * blockDim.x + threadIdx.x;
    if (e >= NEDGE) return;
    atomicAdd(&g_deg_u[eu[e]], 1);
    atomicAdd(&g_deg_m[em[e]], 1);
}

__device__ __forceinline__ void scan_dev(
    const int* __restrict__ deg, int* __restrict__ off,
    int* __restrict__ part, int n, int blk)
{
    __shared__ int s[1024];
    int t = threadIdx.x;
    int i = blk * 1024 + t;
    int v = (i < n) ? deg[i] : 0;
    s[t] = v;
    __syncthreads();
    #pragma unroll
    for (int d = 1; d < 1024; d <<= 1) {
        int x = (t >= d) ? s[t - d] : 0;
        __syncthreads();
        s[t] += x;
        __syncthreads();
    }
    if (i < n) off[i] = s[t] - v;
    if (t == 1023) part[blk] = s[1023];
}

#define NBU ((N_USER  + 1023) / 1024)   // 98
#define NBM ((N_MOVIE + 1023) / 1024)   // 20

__global__ __launch_bounds__(1024) void scan_both_kernel() {
    if (blockIdx.x < NBU) scan_dev(g_deg_u, g_off_u, g_part_u, N_USER, blockIdx.x);
    else                  scan_dev(g_deg_m, g_off_m, g_part_m, N_MOVIE, blockIdx.x - NBU);
}

__global__ __launch_bounds__(128) void scan_partials_kernel() {
    __shared__ int s[128];
    int t = threadIdx.x;
    int v = (t < NBU) ? g_part_u[t] : 0;
    s[t] = v;
    __syncthreads();
    #pragma unroll
    for (int d = 1; d < 128; d <<= 1) {
        int x = (t >= d) ? s[t - d] : 0;
        __syncthreads();
        s[t] += x;
        __syncthreads();
    }
    if (t < NBU) g_part_u[t] = s[t] - v;
    __syncthreads();
    v = (t < NBM) ? g_part_m[t] : 0;
    s[t] = v;
    __syncthreads();
    #pragma unroll
    for (int d = 1; d < 128; d <<= 1) {
        int x = (t >= d) ? s[t - d] : 0;
        __syncthreads();
        s[t] += x;
        __syncthreads();
    }
    if (t < NBM) g_part_m[t] = s[t] - v;
}

__global__ __launch_bounds__(256) void add_offsets_both() {
    int i = blockIdx.x * blockDim.x + threadIdx.x;
    if (i < N_USER) {
        int o = g_off_u[i] + g_part_u[i >> 10];
        g_off_u[i] = o;
        g_cur_u[i] = o;
    } else if (i < N_USER + N_MOVIE) {
        int j = i - N_USER;
        int o = g_off_m[j] + g_part_m[j >> 10];
        g_off_m[j] = o;
        g_cur_m[j] = o;
    }
}

__global__ __launch_bounds__(256) void fill_kernel(
    const int* __restrict__ eu, const int* __restrict__ em)
{
    int e = blockIdx.x * blockDim.x + threadIdx.x;
    if (e >= NEDGE) return;
    int u = eu[e], m = em[e];
    int su = atomicAdd(&g_cur_u[u], 1);
    g_adj_u[su] = m;
    int sm = atomicAdd(&g_cur_m[m], 1);
    g_adj_m[sm] = u;
}

// ---------------------------------------------------------------------------
// Subwarp gather-mean (measured: ~80us total)
// ---------------------------------------------------------------------------
#define DEG_CLAMP 2048

template<int D, int SUBW>
__device__ __forceinline__ void gather_dev(
    const float* __restrict__ src, const int* __restrict__ adj,
    const int* __restrict__ off, const int* __restrict__ deg,
    float* __restrict__ dst, int n, int n_src, int gwarp, int lane)
{
    constexpr int NPW = 32 / SUBW;
    constexpr int VEC = D / SUBW;
    const int sw = lane / SUBW;
    const int sl = lane - sw * SUBW;
    const int node = gwarp * NPW + sw;
    const bool valid = node < n;
    const int nd = valid ? node : (n - 1);
    int o = __ldg(&off[nd]);
    o = min(max(o, 0), NEDGE - 1);
    int d = valid ? __ldg(&deg[nd]) : 0;
    d = min(max(d, 0), DEG_CLAMP);

    int dmax = d;
    #pragma unroll
    for (int k = 16; k; k >>= 1)
        dmax = max(dmax, __shfl_xor_sync(0xffffffffu, dmax, k));

    float acc[VEC];
    #pragma unroll
    for (int v = 0; v < VEC; v++) acc[v] = 0.f;

    const int subbase = sw * SUBW;
    for (int base = 0; base < dmax; base += SUBW) {
        int idx = 0;
        int pos = o + base + sl;
        if (base + sl < d && pos < NEDGE) idx = __ldg(&adj[pos]);
        idx = min(max(idx, 0), n_src - 1);
        const int lim = min(dmax - base, SUBW);
        #pragma unroll 4
        for (int i = 0; i < lim; i++) {
            int s = __shfl_sync(0xffffffffu, idx, subbase + i);
            if (base + i < d) {
                const float* row = src + (size_t)s * D + sl * VEC;
                if constexpr (VEC == 8) {
                    float4 a = __ldg((const float4*)row);
                    float4 b = __ldg((const float4*)(row + 4));
                    acc[0] += a.x; acc[1] += a.y; acc[2] += a.z; acc[3] += a.w;
                    acc[4] += b.x; acc[5] += b.y; acc[6] += b.z; acc[7] += b.w;
                } else {
                    float2 a = __ldg((const float2*)row);
                    acc[0] += a.x; acc[1] += a.y;
                }
            }
        }
    }

    if (valid) {
        float sc = 1.0f / (float)max(d, 1);
        float* out = dst + (size_t)node * D + sl * VEC;
        if constexpr (VEC == 8) {
            *(float4*)out       = make_float4(acc[0]*sc, acc[1]*sc, acc[2]*sc, acc[3]*sc);
            *(float4*)(out + 4) = make_float4(acc[4]*sc, acc[5]*sc, acc[6]*sc, acc[7]*sc);
        } else {
            *(float2*)out = make_float2(acc[0]*sc, acc[1]*sc);
        }
    }
}

#define UWARPS ((N_USER + 3) / 4)
#define GA_WARPS (UWARPS + N_MOVIE)

__global__ __launch_bounds__(256) void gatherA(
    const float* __restrict__ x_movie, const float* __restrict__ x_user)
{
    int gw = (blockIdx.x * 256 + threadIdx.x) >> 5;
    int lane = threadIdx.x & 31;
    if (gw < UWARPS) {
        gather_dev<D_IN, 8>(x_movie, g_adj_u, g_off_u, g_deg_u,
                            g_agg_user, N_USER, N_MOVIE, gw, lane);
    } else if (gw < GA_WARPS) {
        gather_dev<D_IN, 32>(x_user, g_adj_m, g_off_m, g_deg_m,
                             g_agg_movie, N_MOVIE, N_USER, gw - UWARPS, lane);
    }
}

#define GB_WARPS ((N_USER + 1) / 2)

__global__ __launch_bounds__(256) void gatherB() {
    int gw = (blockIdx.x * 256 + threadIdx.x) >> 5;
    int lane = threadIdx.x & 31;
    if (gw < GB_WARPS) {
        gather_dev<HID, 16>(g_movieP, g_adj_u, g_off_u, g_deg_u,
                            g_agg_user2, N_USER, N_MOVIE, gw, lane);
    }
}

// ---------------------------------------------------------------------------
// combine4: row-pair-packed f32x2 GEMM, k-step 4 with conflict-free
// LDS.128 weight loads (KP=132: lane stride 132 words -> each 8-lane phase
// covers all 32 banks exactly once).
//   out[M,N] = act( A[M,128] @ W[128,N] (+agg direct) (+bias) )
//   A = [agg|x] (TWO, two K=64 sources) or x (K=128).
// sx[rp][k] = pack2(row_{2rp}[k], row_{2rp+1}[k]); FFMA2 does 2 rows/instr.
// ---------------------------------------------------------------------------
#define KC  128
#define KP  132

template<int N, bool TWO, bool AGG, bool RELU, bool BIAS>
__global__ __launch_bounds__(256) void combine4(
    const float* __restrict__ agg, const float* __restrict__ x,
    const float* __restrict__ Wl, const float* __restrict__ Wr,
    const float* __restrict__ bias,
    float* __restrict__ out, int nrows)
{
    constexpr int CGRP = N / 64;        // col groups (2 for N=128, 1 for N=64)
    constexpr int RGRP = 8 / CGRP;      // row groups
    constexpr int RPW  = 32 / RGRP;     // row-pairs per warp (8 or 4)

    extern __shared__ __align__(16) char smem[];
    float* sW = (float*)smem;                       // [N][KP]
    ULL*   sx = (ULL*)(smem + (size_t)N * KP * 4);  // [32 rp][KC]

    const int tid  = threadIdx.x;
    const int wid  = tid >> 5;
    const int lane = tid & 31;
    const int cg   = wid % CGRP;
    const int rg   = wid / CGRP;
    const int c0   = cg * 64 + lane;
    const int c1   = c0 + 32;

    // Stage weights once per persistent block: sW[c][k] = W[k][c]
    for (int i = tid; i < KC * N; i += 256) {
        int k = i / N, c = i % N;
        float w;
        if constexpr (TWO) {
            w = (k < 64) ? Wl[(size_t)k * N + c] : Wr[(size_t)(k - 64) * N + c];
        } else {
            w = Wr[(size_t)k * N + c];
        }
        sW[(size_t)c * KP + k] = w;
    }

    float b0 = 0.f, b1 = 0.f;
    if constexpr (BIAS) { b0 = bias[c0]; b1 = bias[c1]; }

    const int ntiles = (nrows + 63) / 64;
    for (int tile = blockIdx.x; tile < ntiles; tile += gridDim.x) {
        const int row0 = tile * 64;
        __syncthreads();   // covers initial weight staging too
        // Stage 64 rows as row-pair packs
        for (int i = tid; i < 32 * KC; i += 256) {
            int rp = i >> 7, k = i & 127;
            int ra = min(row0 + 2 * rp,     nrows - 1);
            int rb = min(row0 + 2 * rp + 1, nrows - 1);
            float va, vb;
            if constexpr (TWO) {
                if (k < 64) {
                    va = agg[(size_t)ra * 64 + k];
                    vb = agg[(size_t)rb * 64 + k];
                } else {
                    va = x[(size_t)ra * 64 + (k - 64)];
                    vb = x[(size_t)rb * 64 + (k - 64)];
                }
            } else {
                va = x[(size_t)ra * KC + k];
                vb = x[(size_t)rb * KC + k];
            }
            sx[i] = pack2(va, vb);
        }
        __syncthreads();

        ULL acc[2][RPW];
        #pragma unroll
        for (int r = 0; r < RPW; r++) {
            acc[0][r] = pack2(b0, b0);
            acc[1][r] = pack2(b1, b1);
        }

        const ULL* sxr = sx + (size_t)(rg * RPW) * KC;
        const float* w0p = sW + (size_t)c0 * KP;
        const float* w1p = sW + (size_t)c1 * KP;

        #pragma unroll 4
        for (int k = 0; k < KC; k += 4) {
            float4 w0 = *(const float4*)(w0p + k);   // LDS.128, conflict-free
            float4 w1 = *(const float4*)(w1p + k);
            ULL w00 = pack2(w0.x, w0.x), w01 = pack2(w0.y, w0.y);
            ULL w02 = pack2(w0.z, w0.z), w03 = pack2(w0.w, w0.w);
            ULL w10 = pack2(w1.x, w1.x), w11 = pack2(w1.y, w1.y);
            ULL w12 = pack2(w1.z, w1.z), w13 = pack2(w1.w, w1.w);
            #pragma unroll
            for (int r = 0; r < RPW; r++) {
                ulonglong2 xa = *(const ulonglong2*)(sxr + (size_t)r * KC + k);
                ulonglong2 xb = *(const ulonglong2*)(sxr + (size_t)r * KC + k + 2);
                acc[0][r] = ffma2u(xa.x, w00, acc[0][r]);
                acc[0][r] = ffma2u(xa.y, w01, acc[0][r]);
                acc[0][r] = ffma2u(xb.x, w02, acc[0][r]);
                acc[0][r] = ffma2u(xb.y, w03, acc[0][r]);
                acc[1][r] = ffma2u(xa.x, w10, acc[1][r]);
                acc[1][r] = ffma2u(xa.y, w11, acc[1][r]);
                acc[1][r] = ffma2u(xb.x, w12, acc[1][r]);
                acc[1][r] = ffma2u(xb.y, w13, acc[1][r]);
            }
        }

        // Epilogue: acc[j][r] = (out[rowa][cj], out[rowb][cj])
        #pragma unroll
        for (int r = 0; r < RPW; r++) {
            int rowa = row0 + (rg * RPW + r) * 2;
            int rowb = rowa + 1;
            #pragma unroll
            for (int j = 0; j < 2; j++) {
                int c = (j == 0) ? c0 : c1;
                float2 v = unpack2(acc[j][r]);
                if (rowa < nrows) {
                    float o = v.x;
                    if constexpr (AGG) o += agg[(size_t)rowa * N + c];
                    if constexpr (RELU) o = fmaxf(o, 0.f);
                    out[(size_t)rowa * N + c] = o;
                }
                if (rowb < nrows) {
                    float o = v.y;
                    if constexpr (AGG) o += agg[(size_t)rowb * N + c];
                    if constexpr (RELU) o = fmaxf(o, 0.f);
                    out[(size_t)rowb * N + c] = o;
                }
            }
        }
    }
}

// ---------------------------------------------------------------------------
// kernel_launch (R10 structure; combine3 -> combine4)
// ---------------------------------------------------------------------------
extern "C" void kernel_launch(void* const* d_in, const int* in_sizes, int n_in,
                              void* d_out, int out_size) {
    const float* x_user  = (const float*)d_in[0];
    const float* x_movie = (const float*)d_in[1];
    const int*   eu      = (const int*)d_in[2];
    const int*   em      = (const int*)d_in[3];
    const float* W1l     = (const float*)d_in[4];
    const float* W1r     = (const float*)d_in[5];
    const float* b1      = (const float*)d_in[6];
    const float* W2l     = (const float*)d_in[7];
    const float* W2r     = (const float*)d_in[8];
    const float* b2      = (const float*)d_in[9];
    const float* W3l     = (const float*)d_in[10];
    const float* W3r     = (const float*)d_in[11];
    const float* b3      = (const float*)d_in[12];
    const float* Wlin1   = (const float*)d_in[13];
    const float* blin1   = (const float*)d_in[14];
    const float* Wlin2   = (const float*)d_in[15];
    const float* blin2   = (const float*)d_in[16];

    float* out_user  = (float*)d_out;
    float* out_movie = out_user + (size_t)N_USER * OUT_D;

    float *p_agg_user, *p_agg_movie, *p_agg_user2;
    float *p_user_x, *p_movie_x, *p_movieP, *p_user_h;
    cudaGetSymbolAddress((void**)&p_agg_user,  g_agg_user);
    cudaGetSymbolAddress((void**)&p_agg_movie, g_agg_movie);
    cudaGetSymbolAddress((void**)&p_agg_user2, g_agg_user2);
    cudaGetSymbolAddress((void**)&p_user_x,    g_user_x);
    cudaGetSymbolAddress((void**)&p_movie_x,   g_movie_x);
    cudaGetSymbolAddress((void**)&p_movieP,    g_movieP);
    cudaGetSymbolAddress((void**)&p_user_h,    g_user_h);

    // smem: weights [N][132] floats + x-pairs [32][128] ULL
    const int SM4_128 = 128 * KP * 4 + 32 * KC * 8;   // 67584 + 32768 = 100352
    const int SM4_64  = 64  * KP * 4 + 32 * KC * 8;   // 33792 + 32768 = 66560

    cudaFuncSetAttribute((const void*)combine4<128, true,  false, true,  true>,
                         cudaFuncAttributeMaxDynamicSharedMemorySize, SM4_128);
    cudaFuncSetAttribute((const void*)combine4<128, false, false, false, false>,
                         cudaFuncAttributeMaxDynamicSharedMemorySize, SM4_128);
    cudaFuncSetAttribute((const void*)combine4<128, false, true,  true,  true>,
                         cudaFuncAttributeMaxDynamicSharedMemorySize, SM4_128);
    cudaFuncSetAttribute((const void*)combine4<64,  false, false, false, true>,
                         cudaFuncAttributeMaxDynamicSharedMemorySize, SM4_64);

    const int GRID = 296;   // 2 persistent blocks/SM

    // CSR build
    zero_counts<<<(N_USER + 255) / 256, 256>>>();
    hist_kernel<<<(NEDGE + 255) / 256, 256>>>(eu, em);
    scan_both_kernel<<<NBU + NBM, 1024>>>();
    scan_partials_kernel<<<1, 128>>>();
    add_offsets_both<<<(N_USER + N_MOVIE + 255) / 256, 256>>>();
    fill_kernel<<<(NEDGE + 255) / 256, 256>>>(eu, em);

    // conv1 + conv2 aggregation (fused subwarp gathers)
    gatherA<<<(GA_WARPS * 32 + 255) / 256, 256>>>(x_movie, x_user);

    // conv1: user_x = relu([agg_user|x_user] @ [W1l;W1r] + b1)
    combine4<128, true, false, true, true><<<GRID, 256, SM4_128>>>(
        p_agg_user, x_user, W1l, W1r, b1, p_user_x, N_USER);

    // conv2: movie_x = relu([agg_movie|x_movie] @ [W2l;W2r] + b2)
    combine4<128, true, false, true, true><<<GRID, 256, SM4_128>>>(
        p_agg_movie, x_movie, W2l, W2r, b2, p_movie_x, N_MOVIE);

    // movieP = movie_x @ W3l (projected before aggregation)
    combine4<128, false, false, false, false><<<GRID, 256, SM4_128>>>(
        nullptr, p_movie_x, nullptr, W3l, nullptr, p_movieP, N_MOVIE);

    // conv3 aggregation (subwarp gather of projected features)
    gatherB<<<(GB_WARPS * 32 + 255) / 256, 256>>>();

    // conv3: user_h = relu(agg_user2 + user_x @ W3r + b3)
    combine4<128, false, true, true, true><<<GRID, 256, SM4_128>>>(
        p_agg_user2, p_user_x, nullptr, W3r, b3, p_user_h, N_USER);

    // out_user = user_h @ Wlin1 + blin1
    combine4<64, false, false, false, true><<<GRID, 256, SM4_64>>>(
        nullptr, p_user_h, nullptr, Wlin1, blin1, out_user, N_USER);

    // out_movie = movie_x @ Wlin2 + blin2
    combine4<64, false, false, false, true><<<GRID, 256, SM4_64>>>(
        nullptr, p_movie_x, nullptr, Wlin2, blin2, out_movie, N_MOVIE);
}

// round 17
// speedup vs baseline: 1.9761x; 1.0275x over previous
#include <cuda_runtime.h>
#include <cstddef>

#define N_USER  100000
#define N_MOVIE 20000
#define D_IN    64
#define HID     128
#define OUT_D   64
#define NEDGE   600000

typedef unsigned long long ULL;

// ---------------------------------------------------------------------------
// Scratch
// ---------------------------------------------------------------------------
__device__ int g_deg_u[N_USER];
__device__ int g_deg_m[N_MOVIE];
__device__ int g_off_u[N_USER];
__device__ int g_off_m[N_MOVIE];
__device__ int g_cur_u[N_USER];
__device__ int g_cur_m[N_MOVIE];
__device__ int g_adj_u[NEDGE];
__device__ int g_adj_m[NEDGE];
__device__ int g_part_u[128];
__device__ int g_part_m[32];

__device__ float g_agg_user [N_USER  * D_IN];
__device__ float g_agg_movie[N_MOVIE * D_IN];
__device__ float g_agg_user2[N_USER  * HID];
__device__ float g_user_x  [N_USER  * HID];
__device__ float g_movie_x [N_MOVIE * HID];
__device__ float g_movieP  [N_MOVIE * HID];
__device__ float g_user_h  [N_USER  * HID];

// ---------------------------------------------------------------------------
// Packed f32x2 helpers
// ---------------------------------------------------------------------------
__device__ __forceinline__ ULL pack2(float x, float y) {
    ULL r;
    asm("mov.b64 %0, {%1, %2};" : "=l"(r) : "f"(x), "f"(y));
    return r;
}
__device__ __forceinline__ float2 unpack2(ULL v) {
    float2 r;
    asm("mov.b64 {%0, %1}, %2;" : "=f"(r.x), "=f"(r.y) : "l"(v));
    return r;
}
__device__ __forceinline__ ULL ffma2u(ULL a, ULL b, ULL c) {
    ULL d;
    asm("fma.rn.f32x2 %0, %1, %2, %3;" : "=l"(d) : "l"(a), "l"(b), "l"(c));
    return d;
}

// ---------------------------------------------------------------------------
// CSR build (measured ~50us)
// ---------------------------------------------------------------------------
__global__ void zero_counts() {
    int i = blockIdx.x * blockDim.x + threadIdx.x;
    if (i < N_USER)  g_deg_u[i] = 0;
    if (i < N_MOVIE) g_deg_m[i] = 0;
}

__global__ __launch_bounds__(256) void hist_kernel(
    const int* __restrict__ eu, const int* __restrict__ em)
{
    int e = blockIdx.x * blockDim.x + threadIdx.x;
    if (e >= NEDGE) return;
    atomicAdd(&g_deg_u[eu[e]], 1);
    atomicAdd(&g_deg_m[em[e]], 1);
}

__device__ __forceinline__ void scan_dev(
    const int* __restrict__ deg, int* __restrict__ off,
    int* __restrict__ part, int n, int blk)
{
    __shared__ int s[1024];
    int t = threadIdx.x;
    int i = blk * 1024 + t;
    int v = (i < n) ? deg[i] : 0;
    s[t] = v;
    __syncthreads();
    #pragma unroll
    for (int d = 1; d < 1024; d <<= 1) {
        int x = (t >= d) ? s[t - d] : 0;
        __syncthreads();
        s[t] += x;
        __syncthreads();
    }
    if (i < n) off[i] = s[t] - v;
    if (t == 1023) part[blk] = s[1023];
}

#define NBU ((N_USER  + 1023) / 1024)   // 98
#define NBM ((N_MOVIE + 1023) / 1024)   // 20

__global__ __launch_bounds__(1024) void scan_both_kernel() {
    if (blockIdx.x < NBU) scan_dev(g_deg_u, g_off_u, g_part_u, N_USER, blockIdx.x);
    else                  scan_dev(g_deg_m, g_off_m, g_part_m, N_MOVIE, blockIdx.x - NBU);
}

__global__ __launch_bounds__(128) void scan_partials_kernel() {
    __shared__ int s[128];
    int t = threadIdx.x;
    int v = (t < NBU) ? g_part_u[t] : 0;
    s[t] = v;
    __syncthreads();
    #pragma unroll
    for (int d = 1; d < 128; d <<= 1) {
        int x = (t >= d) ? s[t - d] : 0;
        __syncthreads();
        s[t] += x;
        __syncthreads();
    }
    if (t < NBU) g_part_u[t] = s[t] - v;
    __syncthreads();
    v = (t < NBM) ? g_part_m[t] : 0;
    s[t] = v;
    __syncthreads();
    #pragma unroll
    for (int d = 1; d < 128; d <<= 1) {
        int x = (t >= d) ? s[t - d] : 0;
        __syncthreads();
        s[t] += x;
        __syncthreads();
    }
    if (t < NBM) g_part_m[t] = s[t] - v;
}

__global__ __launch_bounds__(256) void add_offsets_both() {
    int i = blockIdx.x * blockDim.x + threadIdx.x;
    if (i < N_USER) {
        int o = g_off_u[i] + g_part_u[i >> 10];
        g_off_u[i] = o;
        g_cur_u[i] = o;
    } else if (i < N_USER + N_MOVIE) {
        int j = i - N_USER;
        int o = g_off_m[j] + g_part_m[j >> 10];
        g_off_m[j] = o;
        g_cur_m[j] = o;
    }
}

__global__ __launch_bounds__(256) void fill_kernel(
    const int* __restrict__ eu, const int* __restrict__ em)
{
    int e = blockIdx.x * blockDim.x + threadIdx.x;
    if (e >= NEDGE) return;
    int u = eu[e], m = em[e];
    int su = atomicAdd(&g_cur_u[u], 1);
    g_adj_u[su] = m;
    int sm = atomicAdd(&g_cur_m[m], 1);
    g_adj_m[sm] = u;
}

// ---------------------------------------------------------------------------
// Subwarp gather-mean (measured: ~80us total)
// ---------------------------------------------------------------------------
#define DEG_CLAMP 2048

template<int D, int SUBW>
__device__ __forceinline__ void gather_dev(
    const float* __restrict__ src, const int* __restrict__ adj,
    const int* __restrict__ off, const int* __restrict__ deg,
    float* __restrict__ dst, int n, int n_src, int gwarp, int lane)
{
    constexpr int NPW = 32 / SUBW;
    constexpr int VEC = D / SUBW;
    const int sw = lane / SUBW;
    const int sl = lane - sw * SUBW;
    const int node = gwarp * NPW + sw;
    const bool valid = node < n;
    const int nd = valid ? node : (n - 1);
    int o = __ldg(&off[nd]);
    o = min(max(o, 0), NEDGE - 1);
    int d = valid ? __ldg(&deg[nd]) : 0;
    d = min(max(d, 0), DEG_CLAMP);

    int dmax = d;
    #pragma unroll
    for (int k = 16; k; k >>= 1)
        dmax = max(dmax, __shfl_xor_sync(0xffffffffu, dmax, k));

    float acc[VEC];
    #pragma unroll
    for (int v = 0; v < VEC; v++) acc[v] = 0.f;

    const int subbase = sw * SUBW;
    for (int base = 0; base < dmax; base += SUBW) {
        int idx = 0;
        int pos = o + base + sl;
        if (base + sl < d && pos < NEDGE) idx = __ldg(&adj[pos]);
        idx = min(max(idx, 0), n_src - 1);
        const int lim = min(dmax - base, SUBW);
        #pragma unroll 4
        for (int i = 0; i < lim; i++) {
            int s = __shfl_sync(0xffffffffu, idx, subbase + i);
            if (base + i < d) {
                const float* row = src + (size_t)s * D + sl * VEC;
                if constexpr (VEC == 8) {
                    float4 a = __ldg((const float4*)row);
                    float4 b = __ldg((const float4*)(row + 4));
                    acc[0] += a.x; acc[1] += a.y; acc[2] += a.z; acc[3] += a.w;
                    acc[4] += b.x; acc[5] += b.y; acc[6] += b.z; acc[7] += b.w;
                } else {
                    float2 a = __ldg((const float2*)row);
                    acc[0] += a.x; acc[1] += a.y;
                }
            }
        }
    }

    if (valid) {
        float sc = 1.0f / (float)max(d, 1);
        float* out = dst + (size_t)node * D + sl * VEC;
        if constexpr (VEC == 8) {
            *(float4*)out       = make_float4(acc[0]*sc, acc[1]*sc, acc[2]*sc, acc[3]*sc);
            *(float4*)(out + 4) = make_float4(acc[4]*sc, acc[5]*sc, acc[6]*sc, acc[7]*sc);
        } else {
            *(float2*)out = make_float2(acc[0]*sc, acc[1]*sc);
        }
    }
}

#define UWARPS ((N_USER + 3) / 4)
#define GA_WARPS (UWARPS + N_MOVIE)

__global__ __launch_bounds__(256) void gatherA(
    const float* __restrict__ x_movie, const float* __restrict__ x_user)
{
    int gw = (blockIdx.x * 256 + threadIdx.x) >> 5;
    int lane = threadIdx.x & 31;
    if (gw < UWARPS) {
        gather_dev<D_IN, 8>(x_movie, g_adj_u, g_off_u, g_deg_u,
                            g_agg_user, N_USER, N_MOVIE, gw, lane);
    } else if (gw < GA_WARPS) {
        gather_dev<D_IN, 32>(x_user, g_adj_m, g_off_m, g_deg_m,
                             g_agg_movie, N_MOVIE, N_USER, gw - UWARPS, lane);
    }
}

#define GB_WARPS ((N_USER + 1) / 2)

__global__ __launch_bounds__(256) void gatherB() {
    int gw = (blockIdx.x * 256 + threadIdx.x) >> 5;
    int lane = threadIdx.x & 31;
    if (gw < GB_WARPS) {
        gather_dev<HID, 16>(g_movieP, g_adj_u, g_off_u, g_deg_u,
                            g_agg_user2, N_USER, N_MOVIE, gw, lane);
    }
}

// ---------------------------------------------------------------------------
// combine5: combine4 (R14, measured in the 461us pipeline) with VECTORIZED
// staging: per thread 4 iterations of 2x LDG.128 + 2x STS.128 + 4 packs
// (was ~32 scalar LDG + 16 STS.64). k-quads never straddle the 64-boundary
// (4-aligned), all accesses 16B-aligned.
// ---------------------------------------------------------------------------
#define KC  128
#define KP  132

template<int N, bool TWO, bool AGG, bool RELU, bool BIAS>
__global__ __launch_bounds__(256) void combine5(
    const float* __restrict__ agg, const float* __restrict__ x,
    const float* __restrict__ Wl, const float* __restrict__ Wr,
    const float* __restrict__ bias,
    float* __restrict__ out, int nrows)
{
    constexpr int CGRP = N / 64;
    constexpr int RGRP = 8 / CGRP;
    constexpr int RPW  = 32 / RGRP;

    extern __shared__ __align__(16) char smem[];
    float* sW = (float*)smem;                       // [N][KP]
    ULL*   sx = (ULL*)(smem + (size_t)N * KP * 4);  // [32 rp][KC]

    const int tid  = threadIdx.x;
    const int wid  = tid >> 5;
    const int lane = tid & 31;
    const int cg   = wid % CGRP;
    const int rg   = wid / CGRP;
    const int c0   = cg * 64 + lane;
    const int c1   = c0 + 32;

    // Stage weights once per persistent block: sW[c][k] = W[k][c]
    for (int i = tid; i < KC * N; i += 256) {
        int k = i / N, c = i % N;
        float w;
        if constexpr (TWO) {
            w = (k < 64) ? Wl[(size_t)k * N + c] : Wr[(size_t)(k - 64) * N + c];
        } else {
            w = Wr[(size_t)k * N + c];
        }
        sW[(size_t)c * KP + k] = w;
    }

    float b0 = 0.f, b1 = 0.f;
    if constexpr (BIAS) { b0 = bias[c0]; b1 = bias[c1]; }

    const int ntiles = (nrows + 63) / 64;
    for (int tile = blockIdx.x; tile < ntiles; tile += gridDim.x) {
        const int row0 = tile * 64;
        __syncthreads();   // covers initial weight staging too
        // Stage 64 rows as row-pair packs, 4 k at a time (vectorized).
        #pragma unroll
        for (int i = tid; i < 32 * (KC / 4); i += 256) {   // 4 iterations
            int rp = i >> 5, kq = i & 31;
            int k = kq * 4;
            int ra = min(row0 + 2 * rp,     nrows - 1);
            int rb = min(row0 + 2 * rp + 1, nrows - 1);
            const float* A;
            const float* B;
            if constexpr (TWO) {
                if (k < 64) {
                    A = agg + (size_t)ra * 64 + k;
                    B = agg + (size_t)rb * 64 + k;
                } else {
                    A = x + (size_t)ra * 64 + (k - 64);
                    B = x + (size_t)rb * 64 + (k - 64);
                }
            } else {
                A = x + (size_t)ra * KC + k;
                B = x + (size_t)rb * KC + k;
            }
            float4 a = __ldg((const float4*)A);
            float4 b = __ldg((const float4*)B);
            ULL* dst = sx + (size_t)rp * KC + k;
            *(ulonglong2*)(dst)     = make_ulonglong2(pack2(a.x, b.x), pack2(a.y, b.y));
            *(ulonglong2*)(dst + 2) = make_ulonglong2(pack2(a.z, b.z), pack2(a.w, b.w));
        }
        __syncthreads();

        ULL acc[2][RPW];
        #pragma unroll
        for (int r = 0; r < RPW; r++) {
            acc[0][r] = pack2(b0, b0);
            acc[1][r] = pack2(b1, b1);
        }

        const ULL* sxr = sx + (size_t)(rg * RPW) * KC;
        const float* w0p = sW + (size_t)c0 * KP;
        const float* w1p = sW + (size_t)c1 * KP;

        #pragma unroll 4
        for (int k = 0; k < KC; k += 4) {
            float4 w0 = *(const float4*)(w0p + k);   // LDS.128, conflict-free
            float4 w1 = *(const float4*)(w1p + k);
            ULL w00 = pack2(w0.x, w0.x), w01 = pack2(w0.y, w0.y);
            ULL w02 = pack2(w0.z, w0.z), w03 = pack2(w0.w, w0.w);
            ULL w10 = pack2(w1.x, w1.x), w11 = pack2(w1.y, w1.y);
            ULL w12 = pack2(w1.z, w1.z), w13 = pack2(w1.w, w1.w);
            #pragma unroll
            for (int r = 0; r < RPW; r++) {
                ulonglong2 xa = *(const ulonglong2*)(sxr + (size_t)r * KC + k);
                ulonglong2 xb = *(const ulonglong2*)(sxr + (size_t)r * KC + k + 2);
                acc[0][r] = ffma2u(xa.x, w00, acc[0][r]);
                acc[0][r] = ffma2u(xa.y, w01, acc[0][r]);
                acc[0][r] = ffma2u(xb.x, w02, acc[0][r]);
                acc[0][r] = ffma2u(xb.y, w03, acc[0][r]);
                acc[1][r] = ffma2u(xa.x, w10, acc[1][r]);
                acc[1][r] = ffma2u(xa.y, w11, acc[1][r]);
                acc[1][r] = ffma2u(xb.x, w12, acc[1][r]);
                acc[1][r] = ffma2u(xb.y, w13, acc[1][r]);
            }
        }

        // Epilogue
        #pragma unroll
        for (int r = 0; r < RPW; r++) {
            int rowa = row0 + (rg * RPW + r) * 2;
            int rowb = rowa + 1;
            #pragma unroll
            for (int j = 0; j < 2; j++) {
                int c = (j == 0) ? c0 : c1;
                float2 v = unpack2(acc[j][r]);
                if (rowa < nrows) {
                    float o = v.x;
                    if constexpr (AGG) o += agg[(size_t)rowa * N + c];
                    if constexpr (RELU) o = fmaxf(o, 0.f);
                    out[(size_t)rowa * N + c] = o;
                }
                if (rowb < nrows) {
                    float o = v.y;
                    if constexpr (AGG) o += agg[(size_t)rowb * N + c];
                    if constexpr (RELU) o = fmaxf(o, 0.f);
                    out[(size_t)rowb * N + c] = o;
                }
            }
        }
    }
}

// ---------------------------------------------------------------------------
// kernel_launch (R14 structure; combine4 -> combine5; movie grids capped)
// ---------------------------------------------------------------------------
extern "C" void kernel_launch(void* const* d_in, const int* in_sizes, int n_in,
                              void* d_out, int out_size) {
    const float* x_user  = (const float*)d_in[0];
    const float* x_movie = (const float*)d_in[1];
    const int*   eu      = (const int*)d_in[2];
    const int*   em      = (const int*)d_in[3];
    const float* W1l     = (const float*)d_in[4];
    const float* W1r     = (const float*)d_in[5];
    const float* b1      = (const float*)d_in[6];
    const float* W2l     = (const float*)d_in[7];
    const float* W2r     = (const float*)d_in[8];
    const float* b2      = (const float*)d_in[9];
    const float* W3l     = (const float*)d_in[10];
    const float* W3r     = (const float*)d_in[11];
    const float* b3      = (const float*)d_in[12];
    const float* Wlin1   = (const float*)d_in[13];
    const float* blin1   = (const float*)d_in[14];
    const float* Wlin2   = (const float*)d_in[15];
    const float* blin2   = (const float*)d_in[16];

    float* out_user  = (float*)d_out;
    float* out_movie = out_user + (size_t)N_USER * OUT_D;

    float *p_agg_user, *p_agg_movie, *p_agg_user2;
    float *p_user_x, *p_movie_x, *p_movieP, *p_user_h;
    cudaGetSymbolAddress((void**)&p_agg_user,  g_agg_user);
    cudaGetSymbolAddress((void**)&p_agg_movie, g_agg_movie);
    cudaGetSymbolAddress((void**)&p_agg_user2, g_agg_user2);
    cudaGetSymbolAddress((void**)&p_user_x,    g_user_x);
    cudaGetSymbolAddress((void**)&p_movie_x,   g_movie_x);
    cudaGetSymbolAddress((void**)&p_movieP,    g_movieP);
    cudaGetSymbolAddress((void**)&p_user_h,    g_user_h);

    const int SM4_128 = 128 * KP * 4 + 32 * KC * 8;   // 100352
    const int SM4_64  = 64  * KP * 4 + 32 * KC * 8;   // 66560

    cudaFuncSetAttribute((const void*)combine5<128, true,  false, true,  true>,
                         cudaFuncAttributeMaxDynamicSharedMemorySize, SM4_128);
    cudaFuncSetAttribute((const void*)combine5<128, false, false, false, false>,
                         cudaFuncAttributeMaxDynamicSharedMemorySize, SM4_128);
    cudaFuncSetAttribute((const void*)combine5<128, false, true,  true,  true>,
                         cudaFuncAttributeMaxDynamicSharedMemorySize, SM4_128);
    cudaFuncSetAttribute((const void*)combine5<64,  false, false, false, true>,
                         cudaFuncAttributeMaxDynamicSharedMemorySize, SM4_64);

    const int GRID = 296;                              // 2 persistent blocks/SM
    const int TILES_M = (N_MOVIE + 63) / 64;           // 313
    const int GRID_M  = (TILES_M < GRID) ? TILES_M : GRID;

    // CSR build
    zero_counts<<<(N_USER + 255) / 256, 256>>>();
    hist_kernel<<<(NEDGE + 255) / 256, 256>>>(eu, em);
    scan_both_kernel<<<NBU + NBM, 1024>>>();
    scan_partials_kernel<<<1, 128>>>();
    add_offsets_both<<<(N_USER + N_MOVIE + 255) / 256, 256>>>();
    fill_kernel<<<(NEDGE + 255) / 256, 256>>>(eu, em);

    // conv1 + conv2 aggregation (fused subwarp gathers)
    gatherA<<<(GA_WARPS * 32 + 255) / 256, 256>>>(x_movie, x_user);

    // conv1: user_x = relu([agg_user|x_user] @ [W1l;W1r] + b1)
    combine5<128, true, false, true, true><<<GRID, 256, SM4_128>>>(
        p_agg_user, x_user, W1l, W1r, b1, p_user_x, N_USER);

    // conv2: movie_x = relu([agg_movie|x_movie] @ [W2l;W2r] + b2)
    combine5<128, true, false, true, true><<<GRID_M, 256, SM4_128>>>(
        p_agg_movie, x_movie, W2l, W2r, b2, p_movie_x, N_MOVIE);

    // movieP = movie_x @ W3l (projected before aggregation)
    combine5<128, false, false, false, false><<<GRID_M, 256, SM4_128>>>(
        nullptr, p_movie_x, nullptr, W3l, nullptr, p_movieP, N_MOVIE);

    // conv3 aggregation (subwarp gather of projected features)
    gatherB<<<(GB_WARPS * 32 + 255) / 256, 256>>>();

    // conv3: user_h = relu(agg_user2 + user_x @ W3r + b3)
    combine5<128, false, true, true, true><<<GRID, 256, SM4_128>>>(
        p_agg_user2, p_user_x, nullptr, W3r, b3, p_user_h, N_USER);

    // out_user = user_h @ Wlin1 + blin1
    combine5<64, false, false, false, true><<<GRID, 256, SM4_64>>>(
        nullptr, p_user_h, nullptr, Wlin1, blin1, out_user, N_USER);

    // out_movie = movie_x @ Wlin2 + blin2
    combine5<64, false, false, false, true><<<GRID_M, 256, SM4_64>>>(
        nullptr, p_movie_x, nullptr, Wlin2, blin2, out_movie, N_MOVIE);
}